// round 1
// baseline (speedup 1.0000x reference)
#include <cuda_runtime.h>

// Problem constants (fixed by the reference)
static constexpr int Bsz = 4;
static constexpr int Tt  = 2048;
static constexpr int KD  = 1024;
static constexpr int H   = 16;
static constexpr int HS  = 64;           // head size
static constexpr int Mrows = Bsz * Tt;   // 8192

// Scratch buffers: __device__ globals (allocation-free rule)
__device__ float g_q[Mrows * KD];
__device__ float g_k[Mrows * KD];
__device__ float g_v[Mrows * KD];
__device__ float g_a[Mrows * KD];

// ---------------------------------------------------------------------------
// NT SGEMM: C[m,n] = sum_k A[m,k] * B[n,k]  (+ optional bias[n])
// A: [M,K] row-major, B: [N,K] row-major (nn.Linear weight), C: [M,N]
// 128x128 block tile, BK=8, 256 threads, 8x8 per thread.
// M,N,K all multiples of 128/8 here, so no bounds checks.
// ---------------------------------------------------------------------------
__global__ __launch_bounds__(256) void sgemm_nt(
    const float* __restrict__ A, const float* __restrict__ B,
    const float* __restrict__ bias, float* __restrict__ C,
    int M, int N, int K)
{
    __shared__ float As[8][128];
    __shared__ float Bs[8][128];

    const int tid  = threadIdx.x;
    const int brow = blockIdx.y;
    const int bcol = blockIdx.x;

    const int lrow  = tid >> 1;          // 0..127
    const int lcol4 = (tid & 1) * 4;     // 0 or 4

    const float* Ap = A + (size_t)(brow * 128 + lrow) * K + lcol4;
    const float* Bp = B + (size_t)(bcol * 128 + lrow) * K + lcol4;

    const int ty = tid >> 4;   // 0..15
    const int tx = tid & 15;   // 0..15

    float acc[8][8];
#pragma unroll
    for (int i = 0; i < 8; i++)
#pragma unroll
        for (int j = 0; j < 8; j++) acc[i][j] = 0.0f;

    for (int k0 = 0; k0 < K; k0 += 8) {
        float4 av = *(const float4*)(Ap + k0);
        float4 bv = *(const float4*)(Bp + k0);
        __syncthreads();   // previous tile fully consumed
        As[lcol4 + 0][lrow] = av.x;
        As[lcol4 + 1][lrow] = av.y;
        As[lcol4 + 2][lrow] = av.z;
        As[lcol4 + 3][lrow] = av.w;
        Bs[lcol4 + 0][lrow] = bv.x;
        Bs[lcol4 + 1][lrow] = bv.y;
        Bs[lcol4 + 2][lrow] = bv.z;
        Bs[lcol4 + 3][lrow] = bv.w;
        __syncthreads();

#pragma unroll
        for (int kk = 0; kk < 8; kk++) {
            float a[8], b[8];
            *(float4*)&a[0] = *(const float4*)&As[kk][ty * 8];
            *(float4*)&a[4] = *(const float4*)&As[kk][ty * 8 + 4];
            *(float4*)&b[0] = *(const float4*)&Bs[kk][tx * 8];
            *(float4*)&b[4] = *(const float4*)&Bs[kk][tx * 8 + 4];
#pragma unroll
            for (int i = 0; i < 8; i++)
#pragma unroll
                for (int j = 0; j < 8; j++)
                    acc[i][j] = fmaf(a[i], b[j], acc[i][j]);
        }
    }

    const int crow = brow * 128 + ty * 8;
    const int ccol = bcol * 128 + tx * 8;
    float bi[8];
#pragma unroll
    for (int j = 0; j < 8; j++) bi[j] = bias ? bias[ccol + j] : 0.0f;

#pragma unroll
    for (int i = 0; i < 8; i++) {
        float4 o0, o1;
        o0.x = acc[i][0] + bi[0]; o0.y = acc[i][1] + bi[1];
        o0.z = acc[i][2] + bi[2]; o0.w = acc[i][3] + bi[3];
        o1.x = acc[i][4] + bi[4]; o1.y = acc[i][5] + bi[5];
        o1.z = acc[i][6] + bi[6]; o1.w = acc[i][7] + bi[7];
        *(float4*)&C[(size_t)(crow + i) * N + ccol]     = o0;
        *(float4*)&C[(size_t)(crow + i) * N + ccol + 4] = o1;
    }
}

// ---------------------------------------------------------------------------
// Flash attention, fp32. One CTA = (b, h, 64 query rows).
// Online softmax over 32 key tiles of 64. scale = 1/sqrt(KD) = 1/32.
// Smem: Qs (transposed, stride 68), KPs (K transposed, then reused for P,
// stride 68), Vs (natural, stride 64). Total 51200 B dynamic.
// Thread layout: 16x16, each thread owns a 4x4 S subtile and 4x4 O subtile.
// ---------------------------------------------------------------------------
__global__ __launch_bounds__(256) void flash_kernel(
    const float* __restrict__ Qg, const float* __restrict__ Kg,
    const float* __restrict__ Vg, float* __restrict__ Og)
{
    extern __shared__ float sm[];
    float* Qs  = sm;                 // [64][68] transposed: Qs[d][row]
    float* KPs = sm + 64 * 68;       // [64][68] K transposed / P natural
    float* Vs  = sm + 2 * 64 * 68;   // [64][64] natural: Vs[key][d]

    const int tid = threadIdx.x;
    const int ty  = tid >> 4;        // 0..15
    const int tx  = tid & 15;        // 0..15
    const int r0  = ty * 4;          // query row offset within tile
    const int c0  = tx * 4;          // key-col / dim-col offset

    const int qt = blockIdx.x;       // query tile 0..31
    const int h  = blockIdx.y;
    const int b  = blockIdx.z;
    const size_t hoff    = (size_t)h * HS;
    const size_t rowbase = (size_t)b * Tt;

    // Load Q tile transposed: Qs[d][row]
#pragma unroll
    for (int i = 0; i < 4; i++) {
        int idx = tid + i * 256;
        int row = idx >> 4;
        int c4  = (idx & 15) * 4;
        float4 v = *(const float4*)&Qg[(rowbase + qt * 64 + row) * KD + hoff + c4];
        Qs[(c4 + 0) * 68 + row] = v.x;
        Qs[(c4 + 1) * 68 + row] = v.y;
        Qs[(c4 + 2) * 68 + row] = v.z;
        Qs[(c4 + 3) * 68 + row] = v.w;
    }

    float mrow[4], lrow[4], o[4][4];
#pragma unroll
    for (int i = 0; i < 4; i++) {
        mrow[i] = -1e30f;
        lrow[i] = 0.0f;
#pragma unroll
        for (int j = 0; j < 4; j++) o[i][j] = 0.0f;
    }

    const float scale = 0.03125f;    // 1/sqrt(1024)

    for (int kt = 0; kt < Tt / 64; kt++) {
        __syncthreads();             // previous P reads done, Q load done (iter 0)
        // Load K tile transposed (KPs[d][key]) and V tile natural (Vs[key][d])
#pragma unroll
        for (int i = 0; i < 4; i++) {
            int idx = tid + i * 256;
            int row = idx >> 4;
            int c4  = (idx & 15) * 4;
            size_t g = (rowbase + kt * 64 + row) * KD + hoff + c4;
            float4 kv = *(const float4*)&Kg[g];
            KPs[(c4 + 0) * 68 + row] = kv.x;
            KPs[(c4 + 1) * 68 + row] = kv.y;
            KPs[(c4 + 2) * 68 + row] = kv.z;
            KPs[(c4 + 3) * 68 + row] = kv.w;
            float4 vv = *(const float4*)&Vg[g];
            *(float4*)&Vs[row * 64 + c4] = vv;
        }
        __syncthreads();

        // S = Q K^T  (4x4 per thread)
        float s[4][4];
#pragma unroll
        for (int i = 0; i < 4; i++)
#pragma unroll
            for (int j = 0; j < 4; j++) s[i][j] = 0.0f;

#pragma unroll 8
        for (int kk = 0; kk < 64; kk++) {
            float a[4], bb[4];
            *(float4*)a  = *(const float4*)&Qs[kk * 68 + r0];
            *(float4*)bb = *(const float4*)&KPs[kk * 68 + c0];
#pragma unroll
            for (int i = 0; i < 4; i++)
#pragma unroll
                for (int j = 0; j < 4; j++)
                    s[i][j] = fmaf(a[i], bb[j], s[i][j]);
        }

        // scale + online softmax
#pragma unroll
        for (int i = 0; i < 4; i++) {
#pragma unroll
            for (int j = 0; j < 4; j++) s[i][j] *= scale;
            float mx = fmaxf(fmaxf(s[i][0], s[i][1]), fmaxf(s[i][2], s[i][3]));
            mx = fmaxf(mx, __shfl_xor_sync(0xffffffffu, mx, 8, 16));
            mx = fmaxf(mx, __shfl_xor_sync(0xffffffffu, mx, 4, 16));
            mx = fmaxf(mx, __shfl_xor_sync(0xffffffffu, mx, 2, 16));
            mx = fmaxf(mx, __shfl_xor_sync(0xffffffffu, mx, 1, 16));
            float mn = fmaxf(mrow[i], mx);
            float alpha = __expf(mrow[i] - mn);
            float rs = 0.0f;
#pragma unroll
            for (int j = 0; j < 4; j++) {
                float p = __expf(s[i][j] - mn);
                s[i][j] = p;
                rs += p;
            }
            rs += __shfl_xor_sync(0xffffffffu, rs, 8, 16);
            rs += __shfl_xor_sync(0xffffffffu, rs, 4, 16);
            rs += __shfl_xor_sync(0xffffffffu, rs, 2, 16);
            rs += __shfl_xor_sync(0xffffffffu, rs, 1, 16);
            lrow[i] = lrow[i] * alpha + rs;
            mrow[i] = mn;
#pragma unroll
            for (int j = 0; j < 4; j++) o[i][j] *= alpha;
        }

        __syncthreads();             // done reading KPs as K
        // write P into KPs, natural layout P[row][key], stride 68
#pragma unroll
        for (int i = 0; i < 4; i++) {
            float4 p4;
            p4.x = s[i][0]; p4.y = s[i][1]; p4.z = s[i][2]; p4.w = s[i][3];
            *(float4*)&KPs[(r0 + i) * 68 + c0] = p4;
        }
        __syncthreads();

        // O += P V
#pragma unroll 8
        for (int kk = 0; kk < 64; kk++) {
            float vv[4];
            *(float4*)vv = *(const float4*)&Vs[kk * 64 + c0];
#pragma unroll
            for (int i = 0; i < 4; i++) {
                float p = KPs[(r0 + i) * 68 + kk];
#pragma unroll
                for (int j = 0; j < 4; j++)
                    o[i][j] = fmaf(p, vv[j], o[i][j]);
            }
        }
    }

    // epilogue: O /= l, write (B,T,H*S) contiguous
#pragma unroll
    for (int i = 0; i < 4; i++) {
        float inv = 1.0f / lrow[i];
        float4 r;
        r.x = o[i][0] * inv; r.y = o[i][1] * inv;
        r.z = o[i][2] * inv; r.w = o[i][3] * inv;
        *(float4*)&Og[(rowbase + qt * 64 + r0 + i) * KD + hoff + c0] = r;
    }
}

// ---------------------------------------------------------------------------
// Launch: qkv projections -> flash attention -> output projection (+bias)
// ---------------------------------------------------------------------------
extern "C" void kernel_launch(void* const* d_in, const int* in_sizes, int n_in,
                              void* d_out, int out_size) {
    const float* x  = (const float*)d_in[0];
    const float* Wk = (const float*)d_in[1];
    const float* Wq = (const float*)d_in[2];
    const float* Wv = (const float*)d_in[3];
    const float* Wu = (const float*)d_in[4];
    const float* bu = (const float*)d_in[5];
    float* out = (float*)d_out;

    float *qb, *kb, *vb, *ab;
    cudaGetSymbolAddress((void**)&qb, g_q);
    cudaGetSymbolAddress((void**)&kb, g_k);
    cudaGetSymbolAddress((void**)&vb, g_v);
    cudaGetSymbolAddress((void**)&ab, g_a);

    const int flash_smem = (2 * 64 * 68 + 64 * 64) * (int)sizeof(float); // 51200
    cudaFuncSetAttribute(flash_kernel,
                         cudaFuncAttributeMaxDynamicSharedMemorySize, flash_smem);

    dim3 gg(KD / 128, Mrows / 128);   // (8, 64)
    dim3 bb(256);

    sgemm_nt<<<gg, bb>>>(x, Wq, nullptr, qb, Mrows, KD, KD);
    sgemm_nt<<<gg, bb>>>(x, Wk, nullptr, kb, Mrows, KD, KD);
    sgemm_nt<<<gg, bb>>>(x, Wv, nullptr, vb, Mrows, KD, KD);

    flash_kernel<<<dim3(Tt / 64, H, Bsz), 256, flash_smem>>>(qb, kb, vb, ab);

    sgemm_nt<<<gg, bb>>>(ab, Wu, bu, out, Mrows, KD, KD);
}

// round 3
// speedup vs baseline: 2.5572x; 2.5572x over previous
#include <cuda_runtime.h>
#include <cuda_bf16.h>
#include <cstdint>

// Problem constants
static constexpr int Bsz = 4;
static constexpr int Tt  = 2048;
static constexpr int KD  = 1024;
static constexpr int HS  = 64;
static constexpr int Mrows = Bsz * Tt;   // 8192
static constexpr int K3  = 3072;         // hi|hi|lo split-K

// Scratch (allocation-free rule)
__device__ float g_q[Mrows * KD];
__device__ float g_k[Mrows * KD];
__device__ float g_v[Mrows * KD];
__device__ float g_a[Mrows * KD];
__device__ __nv_bfloat16 g_xs[(size_t)Mrows * K3];
__device__ __nv_bfloat16 g_as[(size_t)Mrows * K3];
__device__ __nv_bfloat16 g_wqs[(size_t)KD * K3];
__device__ __nv_bfloat16 g_wks[(size_t)KD * K3];
__device__ __nv_bfloat16 g_wvs[(size_t)KD * K3];
__device__ __nv_bfloat16 g_wus[(size_t)KD * K3];

// ---------------------------------------------------------------------------
// helpers (sm_100-safe: ldmatrix + mma.sync + cp.async only)
// ---------------------------------------------------------------------------
__device__ __forceinline__ uint32_t smem_u32(const void* p) {
    uint32_t a;
    asm("{ .reg .u64 t; cvta.to.shared.u64 t, %1; cvt.u32.u64 %0, t; }"
        : "=r"(a) : "l"(p));
    return a;
}
__device__ __forceinline__ void ldsm4(uint32_t& d0, uint32_t& d1,
                                      uint32_t& d2, uint32_t& d3, uint32_t addr) {
    asm volatile("ldmatrix.sync.aligned.m8n8.x4.shared.b16 {%0,%1,%2,%3}, [%4];"
                 : "=r"(d0), "=r"(d1), "=r"(d2), "=r"(d3) : "r"(addr));
}
__device__ __forceinline__ void mma16816(float* c, const uint32_t* a,
                                         uint32_t b0, uint32_t b1) {
    asm volatile(
        "mma.sync.aligned.m16n8k16.row.col.f32.bf16.bf16.f32 "
        "{%0,%1,%2,%3}, {%4,%5,%6,%7}, {%8,%9}, {%0,%1,%2,%3};"
        : "+f"(c[0]), "+f"(c[1]), "+f"(c[2]), "+f"(c[3])
        : "r"(a[0]), "r"(a[1]), "r"(a[2]), "r"(a[3]), "r"(b0), "r"(b1));
}
__device__ __forceinline__ uint32_t pack2(__nv_bfloat16 lo, __nv_bfloat16 hi) {
    __nv_bfloat162 t; t.x = lo; t.y = hi;
    return *(uint32_t*)&t;
}
__device__ __forceinline__ void cpasync16(uint32_t dst, const void* src) {
    asm volatile("cp.async.cg.shared.global [%0], [%1], 16;"
                 :: "r"(dst), "l"(src));
}

// ---------------------------------------------------------------------------
// split3: fp32 [rows,1024] -> bf16 [rows,3072]
// mode=1 (activations): [hi|hi|lo];  mode=0 (weights): [hi|lo|hi]
// ---------------------------------------------------------------------------
__global__ __launch_bounds__(256) void split3(const float* __restrict__ src,
                                              __nv_bfloat16* __restrict__ dst,
                                              int mode) {
    int i = blockIdx.x * blockDim.x + threadIdx.x;
    int m = i >> 9;
    int k2 = (i & 511) * 2;
    float2 f = *(const float2*)(src + (size_t)m * 1024 + k2);
    __nv_bfloat16 h0 = __float2bfloat16(f.x), h1 = __float2bfloat16(f.y);
    __nv_bfloat16 l0 = __float2bfloat16(f.x - __bfloat162float(h0));
    __nv_bfloat16 l1 = __float2bfloat16(f.y - __bfloat162float(h1));
    __nv_bfloat162 hh; hh.x = h0; hh.y = h1;
    __nv_bfloat162 ll; ll.x = l0; ll.y = l1;
    __nv_bfloat162* row = (__nv_bfloat162*)(dst + (size_t)m * K3);
    int p = k2 >> 1;
    row[p] = hh;
    row[p + 512]  = mode ? hh : ll;
    row[p + 1024] = mode ? ll : hh;
}

// ---------------------------------------------------------------------------
// mma.sync bf16 NT GEMM: C[m,n] = sum_k A'[m,k]*B'[n,k], K=3072, +bias
// CTA 128x128, 8 warps (64x32 each), cp.async double-buffered, k-chunk 64.
// smem rows padded to 144B -> conflict-free ldmatrix.
// ---------------------------------------------------------------------------
static constexpr int GSPB  = 144;                 // smem row stride bytes
static constexpr int GBUF  = 128 * GSPB;          // 18432 per operand
static constexpr int GEMM_SMEM = 4 * GBUF;        // 73728 (2 ops x 2 bufs)

__global__ __launch_bounds__(256) void mma_gemm(
    const __nv_bfloat16* __restrict__ A, const __nv_bfloat16* __restrict__ Bw,
    const float* __restrict__ bias, float* __restrict__ C) {
    extern __shared__ char sm[];
    const uint32_t sbase = smem_u32(sm);
    const int tid = threadIdx.x, lane = tid & 31, w = tid >> 5;
    const int wm = w >> 2, wn = w & 3;

    const __nv_bfloat16* Ag = A  + (size_t)blockIdx.y * 128 * K3;
    const __nv_bfloat16* Bg = Bw + (size_t)blockIdx.x * 128 * K3;

    const int lrow = tid >> 3;        // 0..31 (with +32*t)
    const int lch  = tid & 7;         // 16B chunk 0..7

    float acc[4][4][4];
#pragma unroll
    for (int a = 0; a < 4; a++)
#pragma unroll
        for (int b = 0; b < 4; b++)
#pragma unroll
            for (int c = 0; c < 4; c++) acc[a][b][c] = 0.0f;

    const int NC = K3 / 64;   // 48

    // issue chunk 0 into buffer 0
#pragma unroll
    for (int t = 0; t < 4; t++) {
        int row = lrow + t * 32;
        uint32_t dA = sbase + row * GSPB + lch * 16;
        cpasync16(dA,             Ag + (size_t)row * K3 + lch * 8);
        cpasync16(dA + 2 * GBUF,  Bg + (size_t)row * K3 + lch * 8);
    }
    asm volatile("cp.async.commit_group;" ::: "memory");

    for (int c = 0; c < NC; c++) {
        const int buf = c & 1;
        if (c + 1 < NC) {
            const int nb = buf ^ 1;
            const int k0 = (c + 1) * 64;
#pragma unroll
            for (int t = 0; t < 4; t++) {
                int row = lrow + t * 32;
                uint32_t dA = sbase + nb * GBUF + row * GSPB + lch * 16;
                cpasync16(dA,            Ag + (size_t)row * K3 + k0 + lch * 8);
                cpasync16(dA + 2 * GBUF, Bg + (size_t)row * K3 + k0 + lch * 8);
            }
            asm volatile("cp.async.commit_group;" ::: "memory");
            asm volatile("cp.async.wait_group 1;" ::: "memory");
        } else {
            asm volatile("cp.async.wait_group 0;" ::: "memory");
        }
        __syncthreads();

        const uint32_t sA = sbase + buf * GBUF;
        const uint32_t sB = sA + 2 * GBUF;
#pragma unroll
        for (int kt = 0; kt < 4; kt++) {
            uint32_t af[4][4], bf[2][4];
#pragma unroll
            for (int mt = 0; mt < 4; mt++) {
                uint32_t addr = sA + (64 * wm + 16 * mt + (lane & 15)) * GSPB
                              + kt * 32 + (lane >> 4) * 16;
                ldsm4(af[mt][0], af[mt][1], af[mt][2], af[mt][3], addr);
            }
#pragma unroll
            for (int ntp = 0; ntp < 2; ntp++) {
                uint32_t addr = sB + (32 * wn + 16 * ntp + (lane & 7)
                              + ((lane >> 4) << 3)) * GSPB
                              + kt * 32 + ((lane >> 3) & 1) * 16;
                ldsm4(bf[ntp][0], bf[ntp][1], bf[ntp][2], bf[ntp][3], addr);
            }
#pragma unroll
            for (int mt = 0; mt < 4; mt++)
#pragma unroll
                for (int ns = 0; ns < 4; ns++)
                    mma16816(acc[mt][ns], af[mt],
                             bf[ns >> 1][(ns & 1) * 2], bf[ns >> 1][(ns & 1) * 2 + 1]);
        }
        __syncthreads();
    }

    // epilogue
#pragma unroll
    for (int mt = 0; mt < 4; mt++) {
        int row = blockIdx.y * 128 + 64 * wm + 16 * mt + (lane >> 2);
#pragma unroll
        for (int ns = 0; ns < 4; ns++) {
            int col = blockIdx.x * 128 + 32 * wn + 8 * ns + 2 * (lane & 3);
            float b0 = bias ? bias[col] : 0.0f;
            float b1 = bias ? bias[col + 1] : 0.0f;
            float2 v0 = { acc[mt][ns][0] + b0, acc[mt][ns][1] + b1 };
            float2 v1 = { acc[mt][ns][2] + b0, acc[mt][ns][3] + b1 };
            *(float2*)&C[(size_t)row * KD + col]       = v0;
            *(float2*)&C[(size_t)(row + 8) * KD + col] = v1;
        }
    }
}

// ---------------------------------------------------------------------------
// Flash attention on mma.sync bf16 with hi/lo splits.
// CTA = 128 thr (4 warps), 64 query rows, key tiles of 64.
// Qsm [64][136h]: [qh|ql]; Ksm [64][136h]: [kh|kl]; Vt [64 dims][136h]: [vh|vl keys]
// QK: 12 k-tiles (qh*kh, qh*kl, ql*kh); PV: 12 k-tiles (Ph*Vh, Ph*Vl, Pl*Vh).
// ---------------------------------------------------------------------------
static constexpr int FSPB = 272;                  // 136 halves
static constexpr int FQ = 0, FK = 64 * FSPB, FV = 128 * FSPB;
static constexpr int FLASH_SMEM = 192 * FSPB;     // 52224

__global__ __launch_bounds__(128) void flash_mma(
    const float* __restrict__ Qg, const float* __restrict__ Kg,
    const float* __restrict__ Vg, float* __restrict__ Og)
{
    extern __shared__ char sm[];
    const uint32_t sbase = smem_u32(sm);
    const int tid = threadIdx.x, lane = tid & 31, w = tid >> 5;

    const int qt = blockIdx.x;
    const size_t hoff    = (size_t)blockIdx.y * HS;
    const size_t rowbase = (size_t)blockIdx.z * Tt;
    const float scale = 0.03125f;   // 1/sqrt(1024)

    // ---- load Q tile (scaled, split) ----
    const float* Qbase = Qg + (rowbase + qt * 64) * KD + hoff;
#pragma unroll
    for (int i = 0; i < 8; i++) {
        int idx = tid + 128 * i;
        int row = idx >> 4;
        int c4  = (idx & 15) * 4;
        float4 f = *(const float4*)(Qbase + (size_t)row * KD + c4);
        f.x *= scale; f.y *= scale; f.z *= scale; f.w *= scale;
        __nv_bfloat16 h0 = __float2bfloat16(f.x), h1 = __float2bfloat16(f.y);
        __nv_bfloat16 h2 = __float2bfloat16(f.z), h3 = __float2bfloat16(f.w);
        __nv_bfloat16 l0 = __float2bfloat16(f.x - __bfloat162float(h0));
        __nv_bfloat16 l1 = __float2bfloat16(f.y - __bfloat162float(h1));
        __nv_bfloat16 l2 = __float2bfloat16(f.z - __bfloat162float(h2));
        __nv_bfloat16 l3 = __float2bfloat16(f.w - __bfloat162float(h3));
        char* r = sm + FQ + row * FSPB;
        *(uint32_t*)(r + c4 * 2)       = pack2(h0, h1);
        *(uint32_t*)(r + c4 * 2 + 4)   = pack2(h2, h3);
        *(uint32_t*)(r + 128 + c4 * 2)     = pack2(l0, l1);
        *(uint32_t*)(r + 128 + c4 * 2 + 4) = pack2(l2, l3);
    }
    __syncthreads();

    // ---- preload Q fragments: 8 k-tiles [qh0..3, ql0..3] ----
    uint32_t qf[8][4];
#pragma unroll
    for (int kt = 0; kt < 8; kt++) {
        uint32_t addr = sbase + FQ + (16 * w + (lane & 15)) * FSPB
                      + kt * 32 + (lane >> 4) * 16;
        ldsm4(qf[kt][0], qf[kt][1], qf[kt][2], qf[kt][3], addr);
    }

    float O[8][4];
#pragma unroll
    for (int j = 0; j < 8; j++)
#pragma unroll
        for (int q = 0; q < 4; q++) O[j][q] = 0.0f;
    float mA = -1e30f, mB = -1e30f, lA = 0.0f, lB = 0.0f;

    for (int ktile = 0; ktile < Tt / 64; ktile++) {
        __syncthreads();
        // ---- load K tile (split) ----
        const float* Kbase = Kg + (rowbase + ktile * 64) * KD + hoff;
#pragma unroll
        for (int i = 0; i < 8; i++) {
            int idx = tid + 128 * i;
            int row = idx >> 4;
            int c4  = (idx & 15) * 4;
            float4 f = *(const float4*)(Kbase + (size_t)row * KD + c4);
            __nv_bfloat16 h0 = __float2bfloat16(f.x), h1 = __float2bfloat16(f.y);
            __nv_bfloat16 h2 = __float2bfloat16(f.z), h3 = __float2bfloat16(f.w);
            __nv_bfloat16 l0 = __float2bfloat16(f.x - __bfloat162float(h0));
            __nv_bfloat16 l1 = __float2bfloat16(f.y - __bfloat162float(h1));
            __nv_bfloat16 l2 = __float2bfloat16(f.z - __bfloat162float(h2));
            __nv_bfloat16 l3 = __float2bfloat16(f.w - __bfloat162float(h3));
            char* r = sm + FK + row * FSPB;
            *(uint32_t*)(r + c4 * 2)       = pack2(h0, h1);
            *(uint32_t*)(r + c4 * 2 + 4)   = pack2(h2, h3);
            *(uint32_t*)(r + 128 + c4 * 2)     = pack2(l0, l1);
            *(uint32_t*)(r + 128 + c4 * 2 + 4) = pack2(l2, l3);
        }
        // ---- load V tile transposed (split): Vt[dim][keys_h|keys_l] ----
        const float* Vbase = Vg + (rowbase + ktile * 64) * KD + hoff;
#pragma unroll
        for (int i = 0; i < 16; i++) {
            int idx = tid + 128 * i;
            int d  = idx & 63;
            int kp = idx >> 6;          // key pair 0..31
            float v0 = Vbase[(size_t)(2 * kp) * KD + d];
            float v1 = Vbase[(size_t)(2 * kp + 1) * KD + d];
            __nv_bfloat16 h0 = __float2bfloat16(v0), h1 = __float2bfloat16(v1);
            __nv_bfloat16 l0 = __float2bfloat16(v0 - __bfloat162float(h0));
            __nv_bfloat16 l1 = __float2bfloat16(v1 - __bfloat162float(h1));
            char* r = sm + FV + d * FSPB;
            *(uint32_t*)(r + kp * 4)       = pack2(h0, h1);
            *(uint32_t*)(r + 128 + kp * 4) = pack2(l0, l1);
        }
        __syncthreads();

        // ---- S = Q'K'^T : 12 k-tiles ----
        float s[8][4];
#pragma unroll
        for (int j = 0; j < 8; j++)
#pragma unroll
            for (int q = 0; q < 4; q++) s[j][q] = 0.0f;

#pragma unroll
        for (int kt = 0; kt < 12; kt++) {
            const int ai = (kt < 8) ? (kt & 3) + ((kt >> 2) & 1) * 0 : 4 + (kt & 3);
            // kt 0-3 -> qh[kt]; 4-7 -> qh[kt-4]; 8-11 -> ql[kt-8]
            const uint32_t* a = (kt < 4) ? qf[kt] : (kt < 8) ? qf[kt - 4] : qf[4 + (kt - 8)];
            (void)ai;
            const int kb = (kt < 8) ? kt * 32 : (kt - 8) * 32;
#pragma unroll
            for (int ntp = 0; ntp < 4; ntp++) {
                uint32_t b0, b1, b2, b3;
                uint32_t addr = sbase + FK + (16 * ntp + (lane & 7)
                              + ((lane >> 4) << 3)) * FSPB
                              + kb + ((lane >> 3) & 1) * 16;
                ldsm4(b0, b1, b2, b3, addr);
                mma16816(s[2 * ntp],     a, b0, b1);
                mma16816(s[2 * ntp + 1], a, b2, b3);
            }
        }

        // ---- online softmax (rows rA=lane/4, rB=+8) ----
        float mxA = -1e30f, mxB = -1e30f;
#pragma unroll
        for (int j = 0; j < 8; j++) {
            mxA = fmaxf(mxA, fmaxf(s[j][0], s[j][1]));
            mxB = fmaxf(mxB, fmaxf(s[j][2], s[j][3]));
        }
        mxA = fmaxf(mxA, __shfl_xor_sync(0xffffffffu, mxA, 1));
        mxA = fmaxf(mxA, __shfl_xor_sync(0xffffffffu, mxA, 2));
        mxB = fmaxf(mxB, __shfl_xor_sync(0xffffffffu, mxB, 1));
        mxB = fmaxf(mxB, __shfl_xor_sync(0xffffffffu, mxB, 2));
        float mAn = fmaxf(mA, mxA), mBn = fmaxf(mB, mxB);
        float aA = __expf(mA - mAn), aB = __expf(mB - mBn);
        float rsA = 0.0f, rsB = 0.0f;
#pragma unroll
        for (int j = 0; j < 8; j++) {
            s[j][0] = __expf(s[j][0] - mAn);
            s[j][1] = __expf(s[j][1] - mAn);
            s[j][2] = __expf(s[j][2] - mBn);
            s[j][3] = __expf(s[j][3] - mBn);
            rsA += s[j][0] + s[j][1];
            rsB += s[j][2] + s[j][3];
        }
        lA = lA * aA + rsA;
        lB = lB * aB + rsB;
        mA = mAn; mB = mBn;
#pragma unroll
        for (int j = 0; j < 8; j++) {
            O[j][0] *= aA; O[j][1] *= aA;
            O[j][2] *= aB; O[j][3] *= aB;
        }

        // ---- P fragments (hi + lo) in A-frag layout ----
        uint32_t ph[4][4], pl[4][4];
#pragma unroll
        for (int k2 = 0; k2 < 4; k2++) {
            const int j0 = 2 * k2, j1 = 2 * k2 + 1;
            float v[8] = { s[j0][0], s[j0][1], s[j0][2], s[j0][3],
                           s[j1][0], s[j1][1], s[j1][2], s[j1][3] };
            __nv_bfloat16 hh[8], ll[8];
#pragma unroll
            for (int e = 0; e < 8; e++) {
                hh[e] = __float2bfloat16(v[e]);
                ll[e] = __float2bfloat16(v[e] - __bfloat162float(hh[e]));
            }
            ph[k2][0] = pack2(hh[0], hh[1]); ph[k2][1] = pack2(hh[2], hh[3]);
            ph[k2][2] = pack2(hh[4], hh[5]); ph[k2][3] = pack2(hh[6], hh[7]);
            pl[k2][0] = pack2(ll[0], ll[1]); pl[k2][1] = pack2(ll[2], ll[3]);
            pl[k2][2] = pack2(ll[4], ll[5]); pl[k2][3] = pack2(ll[6], ll[7]);
        }

        // ---- O += P'V' : 12 k-tiles ----
#pragma unroll
        for (int kt = 0; kt < 12; kt++) {
            const uint32_t* a = (kt < 8) ? ph[kt & 3] : pl[kt & 3];
            const int vb = (kt < 4) ? kt * 32
                         : (kt < 8) ? 128 + (kt - 4) * 32
                                    : (kt - 8) * 32;
#pragma unroll
            for (int ntp = 0; ntp < 4; ntp++) {
                uint32_t b0, b1, b2, b3;
                uint32_t addr = sbase + FV + (16 * ntp + (lane & 7)
                              + ((lane >> 4) << 3)) * FSPB
                              + vb + ((lane >> 3) & 1) * 16;
                ldsm4(b0, b1, b2, b3, addr);
                mma16816(O[2 * ntp],     a, b0, b1);
                mma16816(O[2 * ntp + 1], a, b2, b3);
            }
        }
    }

    // ---- epilogue ----
    lA += __shfl_xor_sync(0xffffffffu, lA, 1);
    lA += __shfl_xor_sync(0xffffffffu, lA, 2);
    lB += __shfl_xor_sync(0xffffffffu, lB, 1);
    lB += __shfl_xor_sync(0xffffffffu, lB, 2);
    float iA = 1.0f / lA, iB = 1.0f / lB;
    const size_t row = rowbase + qt * 64 + 16 * w + (lane >> 2);
#pragma unroll
    for (int j = 0; j < 8; j++) {
        size_t col = hoff + 8 * j + 2 * (lane & 3);
        float2 v0 = { O[j][0] * iA, O[j][1] * iA };
        float2 v1 = { O[j][2] * iB, O[j][3] * iB };
        *(float2*)&Og[row * KD + col]       = v0;
        *(float2*)&Og[(row + 8) * KD + col] = v1;
    }
}

// ---------------------------------------------------------------------------
extern "C" void kernel_launch(void* const* d_in, const int* in_sizes, int n_in,
                              void* d_out, int out_size) {
    const float* x  = (const float*)d_in[0];
    const float* Wk = (const float*)d_in[1];
    const float* Wq = (const float*)d_in[2];
    const float* Wv = (const float*)d_in[3];
    const float* Wu = (const float*)d_in[4];
    const float* bu = (const float*)d_in[5];
    float* out = (float*)d_out;

    float *qb, *kb, *vb, *ab;
    __nv_bfloat16 *xs, *as, *wqs, *wks, *wvs, *wus;
    cudaGetSymbolAddress((void**)&qb, g_q);
    cudaGetSymbolAddress((void**)&kb, g_k);
    cudaGetSymbolAddress((void**)&vb, g_v);
    cudaGetSymbolAddress((void**)&ab, g_a);
    cudaGetSymbolAddress((void**)&xs, g_xs);
    cudaGetSymbolAddress((void**)&as, g_as);
    cudaGetSymbolAddress((void**)&wqs, g_wqs);
    cudaGetSymbolAddress((void**)&wks, g_wks);
    cudaGetSymbolAddress((void**)&wvs, g_wvs);
    cudaGetSymbolAddress((void**)&wus, g_wus);

    cudaFuncSetAttribute(mma_gemm,
                         cudaFuncAttributeMaxDynamicSharedMemorySize, GEMM_SMEM);
    cudaFuncSetAttribute(flash_mma,
                         cudaFuncAttributeMaxDynamicSharedMemorySize, FLASH_SMEM);

    split3<<<(Mrows * 512) / 256, 256>>>(x, xs, 1);
    split3<<<(KD * 512) / 256, 256>>>(Wq, wqs, 0);
    split3<<<(KD * 512) / 256, 256>>>(Wk, wks, 0);
    split3<<<(KD * 512) / 256, 256>>>(Wv, wvs, 0);
    split3<<<(KD * 512) / 256, 256>>>(Wu, wus, 0);

    dim3 gg(KD / 128, Mrows / 128);   // (8, 64)
    mma_gemm<<<gg, 256, GEMM_SMEM>>>(xs, wqs, nullptr, qb);
    mma_gemm<<<gg, 256, GEMM_SMEM>>>(xs, wks, nullptr, kb);
    mma_gemm<<<gg, 256, GEMM_SMEM>>>(xs, wvs, nullptr, vb);

    flash_mma<<<dim3(Tt / 64, 16, Bsz), 128, FLASH_SMEM>>>(qb, kb, vb, ab);

    split3<<<(Mrows * 512) / 256, 256>>>(ab, as, 1);
    mma_gemm<<<gg, 256, GEMM_SMEM>>>(as, wus, bu, out);
}

// round 10
// speedup vs baseline: 2.9036x; 1.1355x over previous
#include <cuda_runtime.h>
#include <cuda_bf16.h>
#include <cstdint>

// Problem constants
static constexpr int Bsz = 4;
static constexpr int Tt  = 2048;
static constexpr int KD  = 1024;
static constexpr int KD2 = 2048;         // split q/k/v row stride: 16 heads x (hi64|lo64)
static constexpr int HS  = 64;
static constexpr int Mrows = Bsz * Tt;   // 8192
static constexpr int K3  = 3072;         // hi|hi|lo split-K

// Scratch (allocation-free rule)
__device__ __nv_bfloat16 g_xs[(size_t)Mrows * K3];      // x split [hi|hi|lo]
__device__ __nv_bfloat16 g_as[(size_t)Mrows * K3];      // attn-out split [hi|hi|lo]
__device__ __nv_bfloat16 g_wqkv[(size_t)3 * KD * K3];   // Wq|Wk|Wv split [hi|lo|hi]
__device__ __nv_bfloat16 g_wus[(size_t)KD * K3];
__device__ __nv_bfloat16 g_qs[(size_t)Mrows * KD2];     // per-head split [h*128: hi|lo]
__device__ __nv_bfloat16 g_ks[(size_t)Mrows * KD2];
__device__ __nv_bfloat16 g_vs[(size_t)Mrows * KD2];

// ---------------------------------------------------------------------------
// helpers (sm_100-safe)
// ---------------------------------------------------------------------------
__device__ __forceinline__ uint32_t smem_u32(const void* p) {
    uint32_t a;
    asm("{ .reg .u64 t; cvta.to.shared.u64 t, %1; cvt.u32.u64 %0, t; }"
        : "=r"(a) : "l"(p));
    return a;
}
__device__ __forceinline__ void ldsm4(uint32_t& d0, uint32_t& d1,
                                      uint32_t& d2, uint32_t& d3, uint32_t addr) {
    asm volatile("ldmatrix.sync.aligned.m8n8.x4.shared.b16 {%0,%1,%2,%3}, [%4];"
                 : "=r"(d0), "=r"(d1), "=r"(d2), "=r"(d3) : "r"(addr));
}
__device__ __forceinline__ void ldsm4t(uint32_t& d0, uint32_t& d1,
                                       uint32_t& d2, uint32_t& d3, uint32_t addr) {
    asm volatile("ldmatrix.sync.aligned.m8n8.x4.trans.shared.b16 {%0,%1,%2,%3}, [%4];"
                 : "=r"(d0), "=r"(d1), "=r"(d2), "=r"(d3) : "r"(addr));
}
__device__ __forceinline__ void mma16816(float* c, const uint32_t* a,
                                         uint32_t b0, uint32_t b1) {
    asm volatile(
        "mma.sync.aligned.m16n8k16.row.col.f32.bf16.bf16.f32 "
        "{%0,%1,%2,%3}, {%4,%5,%6,%7}, {%8,%9}, {%0,%1,%2,%3};"
        : "+f"(c[0]), "+f"(c[1]), "+f"(c[2]), "+f"(c[3])
        : "r"(a[0]), "r"(a[1]), "r"(a[2]), "r"(a[3]), "r"(b0), "r"(b1));
}
__device__ __forceinline__ uint32_t pack2(__nv_bfloat16 lo, __nv_bfloat16 hi) {
    __nv_bfloat162 t; t.x = lo; t.y = hi;
    return *(uint32_t*)&t;
}
__device__ __forceinline__ void cpasync16(uint32_t dst, const void* src) {
    asm volatile("cp.async.cg.shared.global [%0], [%1], 16;"
                 :: "r"(dst), "l"(src));
}
#define CP_COMMIT() asm volatile("cp.async.commit_group;" ::: "memory")
#define CP_WAIT(n)  asm volatile("cp.async.wait_group %0;" :: "n"(n) : "memory")

// ---------------------------------------------------------------------------
// split3: fp32 [rows,1024] -> bf16 [rows,3072]
// mode=1 (activations): [hi|hi|lo];  mode=0 (weights): [hi|lo|hi]
// ---------------------------------------------------------------------------
__global__ __launch_bounds__(256) void split3(const float* __restrict__ src,
                                              __nv_bfloat16* __restrict__ dst,
                                              int mode) {
    int i = blockIdx.x * blockDim.x + threadIdx.x;
    int m = i >> 9;
    int k2 = (i & 511) * 2;
    float2 f = *(const float2*)(src + (size_t)m * 1024 + k2);
    __nv_bfloat16 h0 = __float2bfloat16(f.x), h1 = __float2bfloat16(f.y);
    __nv_bfloat16 l0 = __float2bfloat16(f.x - __bfloat162float(h0));
    __nv_bfloat16 l1 = __float2bfloat16(f.y - __bfloat162float(h1));
    __nv_bfloat162 hh; hh.x = h0; hh.y = h1;
    __nv_bfloat162 ll; ll.x = l0; ll.y = l1;
    __nv_bfloat162* row = (__nv_bfloat162*)(dst + (size_t)m * K3);
    int p = k2 >> 1;
    row[p] = hh;
    row[p + 512]  = mode ? hh : ll;
    row[p + 1024] = mode ? ll : hh;
}

// ---------------------------------------------------------------------------
// mma.sync bf16 NT GEMM, K=3072. mode 0: fp32 C (stride 1024) + bias.
// mode 1: QKV epilogue -> pre-split bf16 per head (Q scaled by 1/32),
//         dst row stride KD2=2048, head h at columns [h*128, h*128+128).
// ---------------------------------------------------------------------------
static constexpr int GSPB  = 144;
static constexpr int GBUF  = 128 * GSPB;
static constexpr int GEMM_SMEM = 4 * GBUF;        // 73728

__global__ __launch_bounds__(256) void mma_gemm(
    const __nv_bfloat16* __restrict__ A, const __nv_bfloat16* __restrict__ Bw,
    const float* __restrict__ bias, float* __restrict__ C,
    __nv_bfloat16* __restrict__ qs, __nv_bfloat16* __restrict__ ks,
    __nv_bfloat16* __restrict__ vs, int mode) {
    extern __shared__ char sm[];
    const uint32_t sbase = smem_u32(sm);
    const int tid = threadIdx.x, lane = tid & 31, w = tid >> 5;
    const int wm = w >> 2, wn = w & 3;

    const __nv_bfloat16* Ag = A  + (size_t)blockIdx.y * 128 * K3;
    const __nv_bfloat16* Bg = Bw + (size_t)blockIdx.x * 128 * K3;

    const int lrow = tid >> 3;
    const int lch  = tid & 7;

    float acc[4][4][4];
#pragma unroll
    for (int a = 0; a < 4; a++)
#pragma unroll
        for (int b = 0; b < 4; b++)
#pragma unroll
            for (int c = 0; c < 4; c++) acc[a][b][c] = 0.0f;

    const int NC = K3 / 64;   // 48

#pragma unroll
    for (int t = 0; t < 4; t++) {
        int row = lrow + t * 32;
        uint32_t dA = sbase + row * GSPB + lch * 16;
        cpasync16(dA,             Ag + (size_t)row * K3 + lch * 8);
        cpasync16(dA + 2 * GBUF,  Bg + (size_t)row * K3 + lch * 8);
    }
    CP_COMMIT();

    for (int c = 0; c < NC; c++) {
        const int buf = c & 1;
        if (c + 1 < NC) {
            const int nb = buf ^ 1;
            const int k0 = (c + 1) * 64;
#pragma unroll
            for (int t = 0; t < 4; t++) {
                int row = lrow + t * 32;
                uint32_t dA = sbase + nb * GBUF + row * GSPB + lch * 16;
                cpasync16(dA,            Ag + (size_t)row * K3 + k0 + lch * 8);
                cpasync16(dA + 2 * GBUF, Bg + (size_t)row * K3 + k0 + lch * 8);
            }
            CP_COMMIT();
            CP_WAIT(1);
        } else {
            CP_WAIT(0);
        }
        __syncthreads();

        const uint32_t sA = sbase + buf * GBUF;
        const uint32_t sB = sA + 2 * GBUF;
#pragma unroll
        for (int kt = 0; kt < 4; kt++) {
            uint32_t af[4][4], bf[2][4];
#pragma unroll
            for (int mt = 0; mt < 4; mt++) {
                uint32_t addr = sA + (64 * wm + 16 * mt + (lane & 15)) * GSPB
                              + kt * 32 + (lane >> 4) * 16;
                ldsm4(af[mt][0], af[mt][1], af[mt][2], af[mt][3], addr);
            }
#pragma unroll
            for (int ntp = 0; ntp < 2; ntp++) {
                uint32_t addr = sB + (32 * wn + 16 * ntp + (lane & 7)
                              + ((lane >> 4) << 3)) * GSPB
                              + kt * 32 + ((lane >> 3) & 1) * 16;
                ldsm4(bf[ntp][0], bf[ntp][1], bf[ntp][2], bf[ntp][3], addr);
            }
#pragma unroll
            for (int mt = 0; mt < 4; mt++)
#pragma unroll
                for (int ns = 0; ns < 4; ns++)
                    mma16816(acc[mt][ns], af[mt],
                             bf[ns >> 1][(ns & 1) * 2], bf[ns >> 1][(ns & 1) * 2 + 1]);
        }
        __syncthreads();
    }

    if (mode == 0) {
#pragma unroll
        for (int mt = 0; mt < 4; mt++) {
            int row = blockIdx.y * 128 + 64 * wm + 16 * mt + (lane >> 2);
#pragma unroll
            for (int ns = 0; ns < 4; ns++) {
                int col = blockIdx.x * 128 + 32 * wn + 8 * ns + 2 * (lane & 3);
                float b0 = bias ? bias[col] : 0.0f;
                float b1 = bias ? bias[col + 1] : 0.0f;
                float2 v0 = { acc[mt][ns][0] + b0, acc[mt][ns][1] + b1 };
                float2 v1 = { acc[mt][ns][2] + b0, acc[mt][ns][3] + b1 };
                *(float2*)&C[(size_t)row * KD + col]       = v0;
                *(float2*)&C[(size_t)(row + 8) * KD + col] = v1;
            }
        }
    } else {
#pragma unroll
        for (int mt = 0; mt < 4; mt++) {
            int row = blockIdx.y * 128 + 64 * wm + 16 * mt + (lane >> 2);
#pragma unroll
            for (int ns = 0; ns < 4; ns++) {
                int colg = blockIdx.x * 128 + 32 * wn + 8 * ns + 2 * (lane & 3);
                int mat = colg >> 10;
                int c1  = colg & 1023;
                int h   = c1 >> 6, d = c1 & 63;
                float sc = (mat == 0) ? 0.03125f : 1.0f;
                __nv_bfloat16* dstb = (mat == 0) ? qs : (mat == 1) ? ks : vs;
                __nv_bfloat16* dst0 = dstb + (size_t)row * KD2 + h * 128 + d;
                __nv_bfloat16* dst1 = dstb + (size_t)(row + 8) * KD2 + h * 128 + d;
                float v0 = acc[mt][ns][0] * sc, v1 = acc[mt][ns][1] * sc;
                float v2 = acc[mt][ns][2] * sc, v3 = acc[mt][ns][3] * sc;
                __nv_bfloat16 h0 = __float2bfloat16(v0), h1 = __float2bfloat16(v1);
                __nv_bfloat16 h2 = __float2bfloat16(v2), h3 = __float2bfloat16(v3);
                __nv_bfloat16 l0 = __float2bfloat16(v0 - __bfloat162float(h0));
                __nv_bfloat16 l1 = __float2bfloat16(v1 - __bfloat162float(h1));
                __nv_bfloat16 l2 = __float2bfloat16(v2 - __bfloat162float(h2));
                __nv_bfloat16 l3 = __float2bfloat16(v3 - __bfloat162float(h3));
                *(uint32_t*)dst0        = pack2(h0, h1);
                *(uint32_t*)(dst0 + 64) = pack2(l0, l1);
                *(uint32_t*)dst1        = pack2(h2, h3);
                *(uint32_t*)(dst1 + 64) = pack2(l2, l3);
            }
        }
    }
}

// ---------------------------------------------------------------------------
// Flash attention, pre-split bf16 inputs (row stride KD2), cp.async
// double-buffered K/V. CTA = 128 thr (4 warps), 64 queries, key tiles of 64.
// Smem row layout: [hi d0..63 | lo d0..63] halves, row stride 272B.
// QK: K as B via ldmatrix (non-trans). PV: V as B via ldmatrix.trans.
// Output: split bf16 [hi|hi|lo] into g_as (K3 columns).
// ---------------------------------------------------------------------------
static constexpr int FSPB = 272;
static constexpr int FQ = 0;
static constexpr int FKV = 64 * FSPB;                 // K0,V0,K1,V1 blocks
static constexpr int FLASH_SMEM = FKV * 5;            // 87040

__global__ __launch_bounds__(128) void flash2(
    const __nv_bfloat16* __restrict__ Qs, const __nv_bfloat16* __restrict__ Ks,
    const __nv_bfloat16* __restrict__ Vs, __nv_bfloat16* __restrict__ Ao)
{
    extern __shared__ char sm[];
    const uint32_t sbase = smem_u32(sm);
    const int tid = threadIdx.x, lane = tid & 31, w = tid >> 5;

    const int qt = blockIdx.x;
    const int h  = blockIdx.y;
    const size_t rowbase = (size_t)blockIdx.z * Tt;
    const size_t hcol = (size_t)h * 128;

    // ---- Q load: 64 rows x 16 chunks of 16B ----
#pragma unroll
    for (int i = 0; i < 8; i++) {
        int id = tid + 128 * i;
        int row = id >> 4, ch = id & 15;
        cpasync16(sbase + FQ + row * FSPB + ch * 16,
                  Qs + (rowbase + qt * 64 + row) * KD2 + hcol + ch * 8);
    }
    CP_COMMIT();

    // ---- K/V tile 0: 64 rows x 16 chunks each ----
    {
#pragma unroll
        for (int i = 0; i < 8; i++) {
            int id = tid + 128 * i;
            int row = id >> 4, ch = id & 15;
            const size_t src = (rowbase + row) * KD2 + hcol + ch * 8;
            cpasync16(sbase + FKV + row * FSPB + ch * 16, Ks + src);
            cpasync16(sbase + 2 * FKV + row * FSPB + ch * 16, Vs + src);
        }
        CP_COMMIT();
    }

    CP_WAIT(1);            // Q ready
    __syncthreads();

    // ---- preload Q fragments: kt 0-3 = qh, 4-7 = ql ----
    uint32_t qf[8][4];
#pragma unroll
    for (int kt = 0; kt < 8; kt++) {
        uint32_t addr = sbase + FQ + (16 * w + (lane & 15)) * FSPB
                      + kt * 32 + (lane >> 4) * 16;
        ldsm4(qf[kt][0], qf[kt][1], qf[kt][2], qf[kt][3], addr);
    }

    float O[8][4];
#pragma unroll
    for (int j = 0; j < 8; j++)
#pragma unroll
        for (int q = 0; q < 4; q++) O[j][q] = 0.0f;
    float mA = -1e30f, mB = -1e30f, lA = 0.0f, lB = 0.0f;

    const int NT = Tt / 64;   // 32
    for (int ktile = 0; ktile < NT; ktile++) {
        // prefetch next tile
        if (ktile + 1 < NT) {
            const int nb = (ktile + 1) & 1;
#pragma unroll
            for (int i = 0; i < 8; i++) {
                int id = tid + 128 * i;
                int row = id >> 4, ch = id & 15;
                const size_t src = (rowbase + (ktile + 1) * 64 + row) * KD2 + hcol + ch * 8;
                cpasync16(sbase + (1 + 2 * nb) * FKV + row * FSPB + ch * 16, Ks + src);
                cpasync16(sbase + (2 + 2 * nb) * FKV + row * FSPB + ch * 16, Vs + src);
            }
            CP_COMMIT();
            CP_WAIT(1);
        } else {
            CP_WAIT(0);
        }
        __syncthreads();

        const uint32_t sK = sbase + (1 + 2 * (ktile & 1)) * FKV;
        const uint32_t sV = sbase + (2 + 2 * (ktile & 1)) * FKV;

        // ---- S = Q'K'^T : 12 k-tiles (qh*kh, qh*kl, ql*kh) ----
        float s[8][4];
#pragma unroll
        for (int j = 0; j < 8; j++)
#pragma unroll
            for (int q = 0; q < 4; q++) s[j][q] = 0.0f;

#pragma unroll
        for (int kt = 0; kt < 12; kt++) {
            const uint32_t* a = qf[(kt < 4) ? kt : kt - 4];
            const int kb = (kt < 8) ? kt * 32 : (kt - 8) * 32;
#pragma unroll
            for (int ntp = 0; ntp < 4; ntp++) {
                uint32_t b0, b1, b2, b3;
                uint32_t addr = sK + (16 * ntp + (lane & 7)
                              + ((lane >> 4) << 3)) * FSPB
                              + kb + ((lane >> 3) & 1) * 16;
                ldsm4(b0, b1, b2, b3, addr);
                mma16816(s[2 * ntp],     a, b0, b1);
                mma16816(s[2 * ntp + 1], a, b2, b3);
            }
        }

        // ---- online softmax ----
        float mxA = -1e30f, mxB = -1e30f;
#pragma unroll
        for (int j = 0; j < 8; j++) {
            mxA = fmaxf(mxA, fmaxf(s[j][0], s[j][1]));
            mxB = fmaxf(mxB, fmaxf(s[j][2], s[j][3]));
        }
        mxA = fmaxf(mxA, __shfl_xor_sync(0xffffffffu, mxA, 1));
        mxA = fmaxf(mxA, __shfl_xor_sync(0xffffffffu, mxA, 2));
        mxB = fmaxf(mxB, __shfl_xor_sync(0xffffffffu, mxB, 1));
        mxB = fmaxf(mxB, __shfl_xor_sync(0xffffffffu, mxB, 2));
        float mAn = fmaxf(mA, mxA), mBn = fmaxf(mB, mxB);
        float aA = __expf(mA - mAn), aB = __expf(mB - mBn);
        float rsA = 0.0f, rsB = 0.0f;
#pragma unroll
        for (int j = 0; j < 8; j++) {
            s[j][0] = __expf(s[j][0] - mAn);
            s[j][1] = __expf(s[j][1] - mAn);
            s[j][2] = __expf(s[j][2] - mBn);
            s[j][3] = __expf(s[j][3] - mBn);
            rsA += s[j][0] + s[j][1];
            rsB += s[j][2] + s[j][3];
        }
        lA = lA * aA + rsA;
        lB = lB * aB + rsB;
        mA = mAn; mB = mBn;
#pragma unroll
        for (int j = 0; j < 8; j++) {
            O[j][0] *= aA; O[j][1] *= aA;
            O[j][2] *= aB; O[j][3] *= aB;
        }

        // ---- P fragments hi/lo ----
        uint32_t ph[4][4], pl[4][4];
#pragma unroll
        for (int k2 = 0; k2 < 4; k2++) {
            const int j0 = 2 * k2, j1 = 2 * k2 + 1;
            float v[8] = { s[j0][0], s[j0][1], s[j0][2], s[j0][3],
                           s[j1][0], s[j1][1], s[j1][2], s[j1][3] };
            __nv_bfloat16 hh[8], ll[8];
#pragma unroll
            for (int e = 0; e < 8; e++) {
                hh[e] = __float2bfloat16(v[e]);
                ll[e] = __float2bfloat16(v[e] - __bfloat162float(hh[e]));
            }
            ph[k2][0] = pack2(hh[0], hh[1]); ph[k2][1] = pack2(hh[2], hh[3]);
            ph[k2][2] = pack2(hh[4], hh[5]); ph[k2][3] = pack2(hh[6], hh[7]);
            pl[k2][0] = pack2(ll[0], ll[1]); pl[k2][1] = pack2(ll[2], ll[3]);
            pl[k2][2] = pack2(ll[4], ll[5]); pl[k2][3] = pack2(ll[6], ll[7]);
        }

        // ---- O += P'V' : terms Ph*Vh, Ph*Vl, Pl*Vh via ldmatrix.trans ----
#pragma unroll
        for (int term = 0; term < 3; term++) {
            const int termB = (term == 1) ? 128 : 0;
#pragma unroll
            for (int kt2 = 0; kt2 < 4; kt2++) {
                const uint32_t* a = (term < 2) ? ph[kt2] : pl[kt2];
#pragma unroll
                for (int dw = 0; dw < 4; dw++) {
                    uint32_t d0, d1, d2, d3;
                    uint32_t addr = sV + (kt2 * 16 + (lane & 7)
                                  + ((lane >> 3) & 1) * 8) * FSPB
                                  + termB + dw * 32 + ((lane >> 4) << 4);
                    ldsm4t(d0, d1, d2, d3, addr);
                    mma16816(O[2 * dw],     a, d0, d1);
                    mma16816(O[2 * dw + 1], a, d2, d3);
                }
            }
        }
        __syncthreads();
    }

    // ---- epilogue: normalize + split write into g_as [hi|hi|lo] ----
    lA += __shfl_xor_sync(0xffffffffu, lA, 1);
    lA += __shfl_xor_sync(0xffffffffu, lA, 2);
    lB += __shfl_xor_sync(0xffffffffu, lB, 1);
    lB += __shfl_xor_sync(0xffffffffu, lB, 2);
    float iA = 1.0f / lA, iB = 1.0f / lB;
    const size_t row0 = rowbase + qt * 64 + 16 * w + (lane >> 2);
#pragma unroll
    for (int j = 0; j < 8; j++) {
        int col = h * 64 + 8 * j + 2 * (lane & 3);
        float v0 = O[j][0] * iA, v1 = O[j][1] * iA;
        float v2 = O[j][2] * iB, v3 = O[j][3] * iB;
        __nv_bfloat16 h0 = __float2bfloat16(v0), h1 = __float2bfloat16(v1);
        __nv_bfloat16 h2 = __float2bfloat16(v2), h3 = __float2bfloat16(v3);
        __nv_bfloat16 l0 = __float2bfloat16(v0 - __bfloat162float(h0));
        __nv_bfloat16 l1 = __float2bfloat16(v1 - __bfloat162float(h1));
        __nv_bfloat16 l2 = __float2bfloat16(v2 - __bfloat162float(h2));
        __nv_bfloat16 l3 = __float2bfloat16(v3 - __bfloat162float(h3));
        __nv_bfloat16* p0 = Ao + row0 * K3 + col;
        __nv_bfloat16* p1 = Ao + (row0 + 8) * K3 + col;
        uint32_t hp0 = pack2(h0, h1), hp1 = pack2(h2, h3);
        *(uint32_t*)p0          = hp0;
        *(uint32_t*)(p0 + 1024) = hp0;
        *(uint32_t*)(p0 + 2048) = pack2(l0, l1);
        *(uint32_t*)p1          = hp1;
        *(uint32_t*)(p1 + 1024) = hp1;
        *(uint32_t*)(p1 + 2048) = pack2(l2, l3);
    }
}

// ---------------------------------------------------------------------------
extern "C" void kernel_launch(void* const* d_in, const int* in_sizes, int n_in,
                              void* d_out, int out_size) {
    const float* x  = (const float*)d_in[0];
    const float* Wk = (const float*)d_in[1];
    const float* Wq = (const float*)d_in[2];
    const float* Wv = (const float*)d_in[3];
    const float* Wu = (const float*)d_in[4];
    const float* bu = (const float*)d_in[5];
    float* out = (float*)d_out;

    __nv_bfloat16 *xs, *as, *wqkv, *wus, *qs, *ks, *vs;
    cudaGetSymbolAddress((void**)&xs, g_xs);
    cudaGetSymbolAddress((void**)&as, g_as);
    cudaGetSymbolAddress((void**)&wqkv, g_wqkv);
    cudaGetSymbolAddress((void**)&wus, g_wus);
    cudaGetSymbolAddress((void**)&qs, g_qs);
    cudaGetSymbolAddress((void**)&ks, g_ks);
    cudaGetSymbolAddress((void**)&vs, g_vs);

    cudaFuncSetAttribute(mma_gemm,
                         cudaFuncAttributeMaxDynamicSharedMemorySize, GEMM_SMEM);
    cudaFuncSetAttribute(flash2,
                         cudaFuncAttributeMaxDynamicSharedMemorySize, FLASH_SMEM);

    // splits: x -> xs; Wq|Wk|Wv -> wqkv; Wu -> wus
    split3<<<(Mrows * 512) / 256, 256>>>(x, xs, 1);
    split3<<<(KD * 512) / 256, 256>>>(Wq, wqkv, 0);
    split3<<<(KD * 512) / 256, 256>>>(Wk, wqkv + (size_t)KD * K3, 0);
    split3<<<(KD * 512) / 256, 256>>>(Wv, wqkv + (size_t)2 * KD * K3, 0);
    split3<<<(KD * 512) / 256, 256>>>(Wu, wus, 0);

    // fused QKV projection -> pre-split bf16 q/k/v (row stride KD2)
    mma_gemm<<<dim3(3 * KD / 128, Mrows / 128), 256, GEMM_SMEM>>>(
        xs, wqkv, nullptr, nullptr, qs, ks, vs, 1);

    // flash attention -> split attn output
    flash2<<<dim3(Tt / 64, 16, Bsz), 128, FLASH_SMEM>>>(qs, ks, vs, as);

    // output projection
    mma_gemm<<<dim3(KD / 128, Mrows / 128), 256, GEMM_SMEM>>>(
        as, wus, bu, out, nullptr, nullptr, nullptr, 0);
}